// round 7
// baseline (speedup 1.0000x reference)
#include <cuda_runtime.h>
#include <cstdint>

#define N_NODES 100000
#define N_EDGES 3200000
#define F_IN    512
#define HID     16
#define N_CLASSES 40
#define CAP     128   // per-node in-edge bucket capacity (deg~Poisson(32): P(>127)~0)

// Scratch (device globals: allocation-free)
__device__ float g_hg[N_NODES * HID];      // hg = relu(x@W1^T+b1) @ Wg^T
__device__ float g_hs[N_NODES * HID];      // hs = hg * dinv
__device__ int   g_cnt[N_NODES];           // in-degree counter / slot allocator
__device__ int   g_slots[N_NODES * CAP];   // bucketed CSR: src ids per dst
__device__ int   g_is64;

// ---------- packed f32x2 helpers (Blackwell) ----------
__device__ __forceinline__ unsigned long long pack2(float x, float y) {
    unsigned long long r;
    asm("mov.b64 %0, {%1,%2};" : "=l"(r) : "f"(x), "f"(y));
    return r;
}
__device__ __forceinline__ void unpack2(unsigned long long v, float& x, float& y) {
    asm("mov.b64 {%0,%1}, %2;" : "=f"(x), "=f"(y) : "l"(v));
}
__device__ __forceinline__ void fma2(unsigned long long& a, unsigned long long b, unsigned long long c) {
    asm("fma.rn.f32x2 %0, %1, %2, %0;" : "+l"(a) : "l"(b), "l"(c));
}

// ---------- prep: zero counters + dtype detect (int64 vs int32 edge_index) ----------
__global__ __launch_bounds__(256) void k_prep(const void* e) {
    int i = blockIdx.x * 256 + threadIdx.x;
    if (i < N_NODES) g_cnt[i] = 0;
    if (blockIdx.x == 0 && threadIdx.x < 64) {
        int t = threadIdx.x;
        const long long* p = (const long long*)e;
        long long v = p[(long long)t * (N_EDGES / 64)];   // max 25.2MB, always in-bounds
        int ok = (v >= 0 && v < N_NODES) ? 1 : 0;
        unsigned m = __ballot_sync(0xFFFFFFFFu, ok);
        __shared__ unsigned sm[2];
        if ((t & 31) == 0) sm[t >> 5] = m;
        __syncthreads();
        if (t == 0) g_is64 = (sm[0] == 0xFFFFFFFFu && sm[1] == 0xFFFFFFFFu) ? 1 : 0;
    }
}

// ---------- K0: hg = (relu(x @ W1^T + b1)) @ Wg^T  -- 2 nodes per thread ----------
__global__ __launch_bounds__(256) void k_gemm1(
    const float4* __restrict__ x4,
    const float* __restrict__ W1,
    const float* __restrict__ b1,
    const float* __restrict__ Wg)
{
    __shared__ ulonglong2 ws[256][8];   // packed W1 pairs: ws[kp][jp]
    __shared__ float sWg[HID * HID];
    __shared__ float sb1[HID];

    int tid = threadIdx.x;
    for (int idx = tid; idx < 256 * 8; idx += 256) {
        int kp = idx >> 3, jp = idx & 7;
        int j0 = jp * 2;
        ulonglong2 v;
        v.x = pack2(W1[j0 * F_IN + 2 * kp],       W1[j0 * F_IN + 2 * kp + 1]);
        v.y = pack2(W1[(j0 + 1) * F_IN + 2 * kp], W1[(j0 + 1) * F_IN + 2 * kp + 1]);
        ws[kp][jp] = v;
    }
    for (int idx = tid; idx < HID * HID; idx += 256) sWg[idx] = Wg[idx];
    for (int idx = tid; idx < HID; idx += 256)       sb1[idx] = b1[idx];
    __syncthreads();

    int node0 = blockIdx.x * 512 + tid;
    int node1 = node0 + 256;
    bool v0 = node0 < N_NODES, v1 = node1 < N_NODES;
    int n0c = v0 ? node0 : N_NODES - 1;
    int n1c = v1 ? node1 : N_NODES - 1;

    unsigned long long acc0[16], acc1[16];
    #pragma unroll
    for (int j = 0; j < 16; j++) { acc0[j] = 0ull; acc1[j] = 0ull; }

    const float4* xr0 = x4 + (long long)n0c * (F_IN / 4);
    const float4* xr1 = x4 + (long long)n1c * (F_IN / 4);
    #pragma unroll 2
    for (int q = 0; q < F_IN / 4; q++) {
        float4 a0 = __ldg(xr0 + q);
        float4 a1 = __ldg(xr1 + q);
        unsigned long long xa0 = pack2(a0.x, a0.y), xb0 = pack2(a0.z, a0.w);
        unsigned long long xa1 = pack2(a1.x, a1.y), xb1 = pack2(a1.z, a1.w);
        #pragma unroll
        for (int jp = 0; jp < 8; jp++) {
            ulonglong2 w = ws[2 * q][jp];
            fma2(acc0[2 * jp],     xa0, w.x);
            fma2(acc0[2 * jp + 1], xa0, w.y);
            fma2(acc1[2 * jp],     xa1, w.x);
            fma2(acc1[2 * jp + 1], xa1, w.y);
        }
        #pragma unroll
        for (int jp = 0; jp < 8; jp++) {
            ulonglong2 w = ws[2 * q + 1][jp];
            fma2(acc0[2 * jp],     xb0, w.x);
            fma2(acc0[2 * jp + 1], xb0, w.y);
            fma2(acc1[2 * jp],     xb1, w.x);
            fma2(acc1[2 * jp + 1], xb1, w.y);
        }
    }

    #pragma unroll
    for (int n = 0; n < 2; n++) {
        if (n == 0 ? !v0 : !v1) continue;
        unsigned long long* acc = n == 0 ? acc0 : acc1;
        int node = n == 0 ? node0 : node1;
        float h1[HID];
        #pragma unroll
        for (int j = 0; j < HID; j++) {
            float lo, hi;
            unpack2(acc[j], lo, hi);
            float v = lo + hi + sb1[j];
            h1[j] = v > 0.f ? v : 0.f;
        }
        float* hgp = g_hg + (long long)node * HID;
        #pragma unroll
        for (int j2 = 0; j2 < HID; j2 += 4) {
            float s0 = 0.f, s1 = 0.f, s2 = 0.f, s3 = 0.f;
            #pragma unroll
            for (int j = 0; j < HID; j++) {
                float hv = h1[j];
                s0 += hv * sWg[(j2 + 0) * HID + j];
                s1 += hv * sWg[(j2 + 1) * HID + j];
                s2 += hv * sWg[(j2 + 2) * HID + j];
                s3 += hv * sWg[(j2 + 3) * HID + j];
            }
            *(float4*)(hgp + j2) = make_float4(s0, s1, s2, s3);
        }
    }
}

// ---------- fill bucketed CSR: 4 edges/thread, batched atomics then stores ----------
__global__ __launch_bounds__(256) void k_fill(const void* __restrict__ e) {
    int t = blockIdx.x * 256 + threadIdx.x;     // group of 4 edges
    if (t >= N_EDGES / 4) return;
    int s[4], d[4];
    if (g_is64) {
        const longlong4* ps = (const longlong4*)e;
        const longlong4* pd = (const longlong4*)((const long long*)e + N_EDGES);
        longlong4 a = ps[t];
        longlong4 b = pd[t];
        s[0] = (int)a.x; s[1] = (int)a.y; s[2] = (int)a.z; s[3] = (int)a.w;
        d[0] = (int)b.x; d[1] = (int)b.y; d[2] = (int)b.z; d[3] = (int)b.w;
    } else {
        const int4* ps = (const int4*)e;
        const int4* pd = (const int4*)((const int*)e + N_EDGES);
        int4 a = ps[t];
        int4 b = pd[t];
        s[0] = a.x; s[1] = a.y; s[2] = a.z; s[3] = a.w;
        d[0] = b.x; d[1] = b.y; d[2] = b.z; d[3] = b.w;
    }
    int pos[4];
    #pragma unroll
    for (int k = 0; k < 4; k++) pos[k] = atomicAdd(&g_cnt[d[k]], 1);
    #pragma unroll
    for (int k = 0; k < 4; k++)
        if (pos[k] < CAP) g_slots[d[k] * CAP + pos[k]] = s[k];
}

// ---------- hs = hg * rsqrt(deg) ----------
__global__ __launch_bounds__(256) void k_dinv() {
    int i = blockIdx.x * 256 + threadIdx.x;
    if (i >= N_NODES) return;
    float dv = rsqrtf((float)(g_cnt[i] + 1));   // +1 self loop
    const float4* h = (const float4*)(g_hg + (long long)i * HID);
    float4* o = (float4*)(g_hs + (long long)i * HID);
    #pragma unroll
    for (int q = 0; q < 4; q++) {
        float4 v = h[q];
        v.x *= dv; v.y *= dv; v.z *= dv; v.w *= dv;
        o[q] = v;
    }
}

// ---------- fused gather + final ----------
// One warp per node. Gather: 4 lanes/edge (float4), slots preloaded + shfl,
// unroll 4 for MLP. Then in-warp: h=relu(out+bg), logits, log_softmax, store.
__global__ __launch_bounds__(256) void k_gather_final(
    const float* __restrict__ W2,
    const float* __restrict__ b2,
    const float* __restrict__ bg,
    float* __restrict__ out)
{
    __shared__ float sW2[N_CLASSES * HID];
    __shared__ float sb2[N_CLASSES];
    __shared__ float sbg[HID];
    int tid = threadIdx.x;
    for (int i = tid; i < N_CLASSES * HID; i += 256) sW2[i] = W2[i];
    if (tid < N_CLASSES) sb2[tid] = b2[tid];
    if (tid < HID) sbg[tid] = bg[tid];
    __syncthreads();

    int warp = (blockIdx.x * 256 + tid) >> 5;
    if (warp >= N_NODES) return;
    int lane = tid & 31;
    int g = lane >> 2;        // edge group 0..7
    int f = lane & 3;         // float4 index 0..3

    int cnt = __ldg(&g_cnt[warp]);
    int m = cnt < CAP ? cnt : CAP;
    const int* slots = g_slots + warp * CAP;

    int s0 = 0, s1 = 0;
    if (lane < m)      s0 = __ldg(slots + lane);
    if (32 + lane < m) s1 = __ldg(slots + 32 + lane);

    float ax = 0.f, ay = 0.f, az = 0.f, aw = 0.f;
    int lim = m < 64 ? m : 64;
    #pragma unroll 4
    for (int e = 0; e < lim; e += 8) {
        int idx = e + g;
        int sv = (e < 32) ? __shfl_sync(0xFFFFFFFFu, s0, idx)
                          : __shfl_sync(0xFFFFFFFFu, s1, idx - 32);
        if (idx < lim) {
            float4 v = __ldg((const float4*)(g_hs + (long long)sv * HID) + f);
            ax += v.x; ay += v.y; az += v.z; aw += v.w;
        }
    }
    for (int e = 64; e < m; e += 8) {   // rare tail (deg > 64)
        int idx = e + g;
        if (idx < m) {
            int sv = __ldg(slots + idx);
            float4 v = __ldg((const float4*)(g_hs + (long long)sv * HID) + f);
            ax += v.x; ay += v.y; az += v.z; aw += v.w;
        }
    }
    #pragma unroll
    for (int off = 4; off < 32; off <<= 1) {
        ax += __shfl_xor_sync(0xFFFFFFFFu, ax, off);
        ay += __shfl_xor_sync(0xFFFFFFFFu, ay, off);
        az += __shfl_xor_sync(0xFFFFFFFFu, az, off);
        aw += __shfl_xor_sync(0xFFFFFFFFu, aw, off);
    }
    // every lane now holds the full sum for feature-quad f = lane&3

    float4 self = __ldg((const float4*)(g_hs + (long long)warp * HID) + f);
    float dv = rsqrtf((float)(cnt + 1));
    float hp[4];
    {
        float t0 = (ax + self.x) * dv + sbg[4 * f + 0];
        float t1 = (ay + self.y) * dv + sbg[4 * f + 1];
        float t2 = (az + self.z) * dv + sbg[4 * f + 2];
        float t3 = (aw + self.w) * dv + sbg[4 * f + 3];
        hp[0] = t0 > 0.f ? t0 : 0.f;
        hp[1] = t1 > 0.f ? t1 : 0.f;
        hp[2] = t2 > 0.f ? t2 : 0.f;
        hp[3] = t3 > 0.f ? t3 : 0.f;
    }

    // broadcast h[16]: lane a (a=0..3) holds h[4a..4a+3]
    float h[HID];
    #pragma unroll
    for (int a = 0; a < 4; a++) {
        #pragma unroll
        for (int b = 0; b < 4; b++)
            h[a * 4 + b] = __shfl_sync(0xFFFFFFFFu, hp[b], a);
    }

    // logits: lane -> class lane; lanes 0..7 also class 32+lane
    float l1 = sb2[lane];
    #pragma unroll
    for (int j = 0; j < HID; j++) l1 += h[j] * sW2[lane * HID + j];
    float l2 = -3.4e38f;
    if (lane < N_CLASSES - 32) {
        l2 = sb2[32 + lane];
        #pragma unroll
        for (int j = 0; j < HID; j++) l2 += h[j] * sW2[(32 + lane) * HID + j];
    }

    float mx = fmaxf(l1, l2);
    #pragma unroll
    for (int off = 16; off >= 1; off >>= 1)
        mx = fmaxf(mx, __shfl_xor_sync(0xFFFFFFFFu, mx, off));
    float ee = __expf(l1 - mx) + (lane < N_CLASSES - 32 ? __expf(l2 - mx) : 0.f);
    #pragma unroll
    for (int off = 16; off >= 1; off >>= 1)
        ee += __shfl_xor_sync(0xFFFFFFFFu, ee, off);
    float lse = __logf(ee) + mx;

    float* o = out + (long long)warp * N_CLASSES;
    o[lane] = l1 - lse;
    if (lane < N_CLASSES - 32) o[32 + lane] = l2 - lse;
}

extern "C" void kernel_launch(void* const* d_in, const int* in_sizes, int n_in,
                              void* d_out, int out_size) {
    const float* x  = (const float*)d_in[0];
    const void*  e  = d_in[1];
    const float* W1 = (const float*)d_in[2];
    const float* b1 = (const float*)d_in[3];
    const float* Wg = (const float*)d_in[4];
    const float* bg = (const float*)d_in[5];
    const float* W2 = (const float*)d_in[6];
    const float* b2 = (const float*)d_in[7];
    float* out = (float*)d_out;

    const int NB_N  = (N_NODES + 255) / 256;
    const int NB_G1 = (N_NODES + 511) / 512;
    const int NB_E4 = (N_EDGES / 4 + 255) / 256;
    const int NB_G  = (N_NODES * 32 + 255) / 256;

    k_prep<<<NB_N, 256>>>(e);
    k_gemm1<<<NB_G1, 256>>>((const float4*)x, W1, b1, Wg);
    k_fill<<<NB_E4, 256>>>(e);
    k_dinv<<<NB_N, 256>>>();
    k_gather_final<<<NB_G, 256>>>(W2, b2, bg, out);
}

// round 8
// speedup vs baseline: 1.0079x; 1.0079x over previous
#include <cuda_runtime.h>
#include <cstdint>

#define N_NODES 100000
#define N_EDGES 3200000
#define F_IN    512
#define HID     16
#define N_CLASSES 40
#define CAP     128   // per-node in-edge bucket capacity (deg~Poisson(32): P(>127)~0)

#define GB_NODES 128  // nodes per gemm block
#define KC4      16   // float4 per k-chunk (64 floats)
#define NCHUNK   8    // 512 / 64

// Scratch (device globals: allocation-free)
__device__ float g_hg[N_NODES * HID];      // hg = relu(x@W1^T+b1) @ Wg^T
__device__ float g_hs[N_NODES * HID];      // hs = hg * dinv
__device__ int   g_cnt[N_NODES];           // in-degree counter / slot allocator
__device__ int   g_slots[N_NODES * CAP];   // bucketed CSR: src ids per dst
__device__ int   g_is64;

// ---------- packed f32x2 helpers (Blackwell) ----------
__device__ __forceinline__ unsigned long long pack2(float x, float y) {
    unsigned long long r;
    asm("mov.b64 %0, {%1,%2};" : "=l"(r) : "f"(x), "f"(y));
    return r;
}
__device__ __forceinline__ void unpack2(unsigned long long v, float& x, float& y) {
    asm("mov.b64 {%0,%1}, %2;" : "=f"(x), "=f"(y) : "l"(v));
}
__device__ __forceinline__ void fma2(unsigned long long& a, unsigned long long b, unsigned long long c) {
    asm("fma.rn.f32x2 %0, %1, %2, %0;" : "+l"(a) : "l"(b), "l"(c));
}

// ---------- prep: zero counters + dtype detect (int64 vs int32 edge_index) ----------
__global__ __launch_bounds__(256) void k_prep(const void* e) {
    int i = blockIdx.x * 256 + threadIdx.x;
    if (i < N_NODES) g_cnt[i] = 0;
    if (blockIdx.x == 0 && threadIdx.x < 64) {
        int t = threadIdx.x;
        const long long* p = (const long long*)e;
        long long v = p[(long long)t * (N_EDGES / 64)];   // max 25.2MB, always in-bounds
        int ok = (v >= 0 && v < N_NODES) ? 1 : 0;
        unsigned m = __ballot_sync(0xFFFFFFFFu, ok);
        __shared__ unsigned sm[2];
        if ((t & 31) == 0) sm[t >> 5] = m;
        __syncthreads();
        if (t == 0) g_is64 = (sm[0] == 0xFFFFFFFFu && sm[1] == 0xFFFFFFFFu) ? 1 : 0;
    }
}

// ---------- K0: hg = (relu(x @ W1^T + b1)) @ Wg^T ----------
// smem-staged x: cooperative coalesced tile loads (256B contiguous per 16 lanes),
// then each thread consumes its own padded smem row. Fixes the nL=32 L1tex
// wavefront explosion of direct row-per-thread LDG.
__global__ __launch_bounds__(GB_NODES) void k_gemm1(
    const float4* __restrict__ x4,
    const float* __restrict__ W1,
    const float* __restrict__ b1,
    const float* __restrict__ Wg)
{
    __shared__ float4 sx[GB_NODES][KC4 + 1];   // +16B row pad: phase-conflict-free
    __shared__ ulonglong2 ws[256][8];          // packed W1 pairs: ws[kp][jp]
    __shared__ float sWg[HID * HID];
    __shared__ float sb1[HID];

    int tid = threadIdx.x;
    for (int idx = tid; idx < 256 * 8; idx += GB_NODES) {
        int kp = idx >> 3, jp = idx & 7;
        int j0 = jp * 2;
        ulonglong2 v;
        v.x = pack2(W1[j0 * F_IN + 2 * kp],       W1[j0 * F_IN + 2 * kp + 1]);
        v.y = pack2(W1[(j0 + 1) * F_IN + 2 * kp], W1[(j0 + 1) * F_IN + 2 * kp + 1]);
        ws[kp][jp] = v;
    }
    for (int idx = tid; idx < HID * HID; idx += GB_NODES) sWg[idx] = Wg[idx];
    for (int idx = tid; idx < HID; idx += GB_NODES)       sb1[idx] = b1[idx];

    int base = blockIdx.x * GB_NODES;
    int node = base + tid;
    bool valid = node < N_NODES;

    unsigned long long acc[16];
    #pragma unroll
    for (int j = 0; j < 16; j++) acc[j] = 0ull;

    #pragma unroll 1
    for (int c = 0; c < NCHUNK; c++) {
        __syncthreads();   // also orders first-chunk stores after weight loads
        // cooperative coalesced load: 16 consecutive lanes -> 256B contiguous
        #pragma unroll
        for (int i = 0; i < KC4; i++) {
            int flat = tid + i * GB_NODES;   // 0..2047
            int n  = flat >> 4;
            int k4 = flat & 15;
            int gn = base + n;
            if (gn >= N_NODES) gn = N_NODES - 1;
            sx[n][k4] = __ldg(x4 + (long long)gn * (F_IN / 4) + c * KC4 + k4);
        }
        __syncthreads();

        #pragma unroll
        for (int q = 0; q < KC4; q++) {
            float4 xv = sx[tid][q];
            unsigned long long xa = pack2(xv.x, xv.y);
            unsigned long long xb = pack2(xv.z, xv.w);
            int kp = c * (KC4 * 2) + q * 2;
            #pragma unroll
            for (int jp = 0; jp < 8; jp++) {
                ulonglong2 w = ws[kp][jp];
                fma2(acc[2 * jp],     xa, w.x);
                fma2(acc[2 * jp + 1], xa, w.y);
            }
            #pragma unroll
            for (int jp = 0; jp < 8; jp++) {
                ulonglong2 w = ws[kp + 1][jp];
                fma2(acc[2 * jp],     xb, w.x);
                fma2(acc[2 * jp + 1], xb, w.y);
            }
        }
    }

    if (!valid) return;

    float h1[HID];
    #pragma unroll
    for (int j = 0; j < HID; j++) {
        float lo, hi;
        unpack2(acc[j], lo, hi);
        float v = lo + hi + sb1[j];
        h1[j] = v > 0.f ? v : 0.f;
    }

    float* hgp = g_hg + (long long)node * HID;
    #pragma unroll
    for (int j2 = 0; j2 < HID; j2 += 4) {
        float s0 = 0.f, s1 = 0.f, s2 = 0.f, s3 = 0.f;
        #pragma unroll
        for (int j = 0; j < HID; j++) {
            float hv = h1[j];
            s0 += hv * sWg[(j2 + 0) * HID + j];
            s1 += hv * sWg[(j2 + 1) * HID + j];
            s2 += hv * sWg[(j2 + 2) * HID + j];
            s3 += hv * sWg[(j2 + 3) * HID + j];
        }
        *(float4*)(hgp + j2) = make_float4(s0, s1, s2, s3);
    }
}

// ---------- fill bucketed CSR: 4 edges/thread, batched atomics then stores ----------
__global__ __launch_bounds__(256) void k_fill(const void* __restrict__ e) {
    int t = blockIdx.x * 256 + threadIdx.x;     // group of 4 edges
    if (t >= N_EDGES / 4) return;
    int s[4], d[4];
    if (g_is64) {
        const longlong4* ps = (const longlong4*)e;
        const longlong4* pd = (const longlong4*)((const long long*)e + N_EDGES);
        longlong4 a = ps[t];
        longlong4 b = pd[t];
        s[0] = (int)a.x; s[1] = (int)a.y; s[2] = (int)a.z; s[3] = (int)a.w;
        d[0] = (int)b.x; d[1] = (int)b.y; d[2] = (int)b.z; d[3] = (int)b.w;
    } else {
        const int4* ps = (const int4*)e;
        const int4* pd = (const int4*)((const int*)e + N_EDGES);
        int4 a = ps[t];
        int4 b = pd[t];
        s[0] = a.x; s[1] = a.y; s[2] = a.z; s[3] = a.w;
        d[0] = b.x; d[1] = b.y; d[2] = b.z; d[3] = b.w;
    }
    int pos[4];
    #pragma unroll
    for (int k = 0; k < 4; k++) pos[k] = atomicAdd(&g_cnt[d[k]], 1);
    #pragma unroll
    for (int k = 0; k < 4; k++)
        if (pos[k] < CAP) g_slots[d[k] * CAP + pos[k]] = s[k];
}

// ---------- hs = hg * rsqrt(deg) ----------
__global__ __launch_bounds__(256) void k_dinv() {
    int i = blockIdx.x * 256 + threadIdx.x;
    if (i >= N_NODES) return;
    float dv = rsqrtf((float)(g_cnt[i] + 1));   // +1 self loop
    const float4* h = (const float4*)(g_hg + (long long)i * HID);
    float4* o = (float4*)(g_hs + (long long)i * HID);
    #pragma unroll
    for (int q = 0; q < 4; q++) {
        float4 v = h[q];
        v.x *= dv; v.y *= dv; v.z *= dv; v.w *= dv;
        o[q] = v;
    }
}

// ---------- fused gather + final (measured ~neutral vs split; keeps 6.4MB off DRAM) ----------
__global__ __launch_bounds__(256) void k_gather_final(
    const float* __restrict__ W2,
    const float* __restrict__ b2,
    const float* __restrict__ bg,
    float* __restrict__ out)
{
    __shared__ float sW2[N_CLASSES * HID];
    __shared__ float sb2[N_CLASSES];
    __shared__ float sbg[HID];
    int tid = threadIdx.x;
    for (int i = tid; i < N_CLASSES * HID; i += 256) sW2[i] = W2[i];
    if (tid < N_CLASSES) sb2[tid] = b2[tid];
    if (tid < HID) sbg[tid] = bg[tid];
    __syncthreads();

    int warp = (blockIdx.x * 256 + tid) >> 5;
    if (warp >= N_NODES) return;
    int lane = tid & 31;
    int g = lane >> 2;        // edge group 0..7
    int f = lane & 3;         // float4 index 0..3

    int cnt = __ldg(&g_cnt[warp]);
    int m = cnt < CAP ? cnt : CAP;
    const int* slots = g_slots + warp * CAP;

    int s0 = 0, s1 = 0;
    if (lane < m)      s0 = __ldg(slots + lane);
    if (32 + lane < m) s1 = __ldg(slots + 32 + lane);

    float ax = 0.f, ay = 0.f, az = 0.f, aw = 0.f;
    int lim = m < 64 ? m : 64;
    #pragma unroll 4
    for (int e = 0; e < lim; e += 8) {
        int idx = e + g;
        int sv = (e < 32) ? __shfl_sync(0xFFFFFFFFu, s0, idx)
                          : __shfl_sync(0xFFFFFFFFu, s1, idx - 32);
        if (idx < lim) {
            float4 v = __ldg((const float4*)(g_hs + (long long)sv * HID) + f);
            ax += v.x; ay += v.y; az += v.z; aw += v.w;
        }
    }
    for (int e = 64; e < m; e += 8) {   // rare tail (deg > 64)
        int idx = e + g;
        if (idx < m) {
            int sv = __ldg(slots + idx);
            float4 v = __ldg((const float4*)(g_hs + (long long)sv * HID) + f);
            ax += v.x; ay += v.y; az += v.z; aw += v.w;
        }
    }
    #pragma unroll
    for (int off = 4; off < 32; off <<= 1) {
        ax += __shfl_xor_sync(0xFFFFFFFFu, ax, off);
        ay += __shfl_xor_sync(0xFFFFFFFFu, ay, off);
        az += __shfl_xor_sync(0xFFFFFFFFu, az, off);
        aw += __shfl_xor_sync(0xFFFFFFFFu, aw, off);
    }

    float4 self = __ldg((const float4*)(g_hs + (long long)warp * HID) + f);
    float dv = rsqrtf((float)(cnt + 1));
    float hp[4];
    {
        float t0 = (ax + self.x) * dv + sbg[4 * f + 0];
        float t1 = (ay + self.y) * dv + sbg[4 * f + 1];
        float t2 = (az + self.z) * dv + sbg[4 * f + 2];
        float t3 = (aw + self.w) * dv + sbg[4 * f + 3];
        hp[0] = t0 > 0.f ? t0 : 0.f;
        hp[1] = t1 > 0.f ? t1 : 0.f;
        hp[2] = t2 > 0.f ? t2 : 0.f;
        hp[3] = t3 > 0.f ? t3 : 0.f;
    }

    float h[HID];
    #pragma unroll
    for (int a = 0; a < 4; a++) {
        #pragma unroll
        for (int b = 0; b < 4; b++)
            h[a * 4 + b] = __shfl_sync(0xFFFFFFFFu, hp[b], a);
    }

    float l1 = sb2[lane];
    #pragma unroll
    for (int j = 0; j < HID; j++) l1 += h[j] * sW2[lane * HID + j];
    float l2 = -3.4e38f;
    if (lane < N_CLASSES - 32) {
        l2 = sb2[32 + lane];
        #pragma unroll
        for (int j = 0; j < HID; j++) l2 += h[j] * sW2[(32 + lane) * HID + j];
    }

    float mx = fmaxf(l1, l2);
    #pragma unroll
    for (int off = 16; off >= 1; off >>= 1)
        mx = fmaxf(mx, __shfl_xor_sync(0xFFFFFFFFu, mx, off));
    float ee = __expf(l1 - mx) + (lane < N_CLASSES - 32 ? __expf(l2 - mx) : 0.f);
    #pragma unroll
    for (int off = 16; off >= 1; off >>= 1)
        ee += __shfl_xor_sync(0xFFFFFFFFu, ee, off);
    float lse = __logf(ee) + mx;

    float* o = out + (long long)warp * N_CLASSES;
    o[lane] = l1 - lse;
    if (lane < N_CLASSES - 32) o[32 + lane] = l2 - lse;
}

extern "C" void kernel_launch(void* const* d_in, const int* in_sizes, int n_in,
                              void* d_out, int out_size) {
    const float* x  = (const float*)d_in[0];
    const void*  e  = d_in[1];
    const float* W1 = (const float*)d_in[2];
    const float* b1 = (const float*)d_in[3];
    const float* Wg = (const float*)d_in[4];
    const float* bg = (const float*)d_in[5];
    const float* W2 = (const float*)d_in[6];
    const float* b2 = (const float*)d_in[7];
    float* out = (float*)d_out;

    const int NB_N  = (N_NODES + 255) / 256;
    const int NB_G1 = (N_NODES + GB_NODES - 1) / GB_NODES;
    const int NB_E4 = (N_EDGES / 4 + 255) / 256;
    const int NB_G  = (N_NODES * 32 + 255) / 256;

    k_prep<<<NB_N, 256>>>(e);
    k_gemm1<<<NB_G1, GB_NODES>>>((const float4*)x, W1, b1, Wg);
    k_fill<<<NB_E4, 256>>>(e);
    k_dinv<<<NB_N, 256>>>();
    k_gather_final<<<NB_G, 256>>>(W2, b2, bg, out);
}

// round 9
// speedup vs baseline: 1.1989x; 1.1896x over previous
#include <cuda_runtime.h>
#include <cstdint>

#define N_NODES 100000
#define N_EDGES 3200000
#define F_IN    512
#define HID     16
#define N_CLASSES 40
#define CAP     128   // per-node in-edge bucket capacity (deg~Poisson(32): P(>127)~0)

// Scratch (device globals: allocation-free)
__device__ float g_hg[N_NODES * HID];      // hg = relu(x@W1^T+b1) @ Wg^T
__device__ float g_hs[N_NODES * HID];      // hs = hg * dinv
__device__ int   g_cnt[N_NODES];           // in-degree counter / slot allocator
__device__ int   g_slots[N_NODES * CAP];   // bucketed CSR: src ids per dst
__device__ int   g_is64;

// ---------- packed f32x2 helpers (Blackwell) ----------
__device__ __forceinline__ unsigned long long pack2(float x, float y) {
    unsigned long long r;
    asm("mov.b64 %0, {%1,%2};" : "=l"(r) : "f"(x), "f"(y));
    return r;
}
__device__ __forceinline__ void unpack2(unsigned long long v, float& x, float& y) {
    asm("mov.b64 {%0,%1}, %2;" : "=f"(x), "=f"(y) : "l"(v));
}
__device__ __forceinline__ void fma2(unsigned long long& a, unsigned long long b, unsigned long long c) {
    asm("fma.rn.f32x2 %0, %1, %2, %0;" : "+l"(a) : "l"(b), "l"(c));
}

// ---------- prep: zero counters + dtype detect (int64 vs int32 edge_index) ----------
__global__ __launch_bounds__(256) void k_prep(const void* e) {
    int i = blockIdx.x * 256 + threadIdx.x;
    if (i < N_NODES) g_cnt[i] = 0;
    if (blockIdx.x == 0 && threadIdx.x < 64) {
        int t = threadIdx.x;
        const long long* p = (const long long*)e;
        long long v = p[(long long)t * (N_EDGES / 64)];   // max 25.2MB, always in-bounds
        int ok = (v >= 0 && v < N_NODES) ? 1 : 0;
        unsigned m = __ballot_sync(0xFFFFFFFFu, ok);
        __shared__ unsigned sm[2];
        if ((t & 31) == 0) sm[t >> 5] = m;
        __syncthreads();
        if (t == 0) g_is64 = (sm[0] == 0xFFFFFFFFu && sm[1] == 0xFFFFFFFFu) ? 1 : 0;
    }
}

// ---------- K0: hg = (relu(x @ W1^T + b1)) @ Wg^T ----------
// 1 node/thread, direct LDG of own row, software prefetch depth 8 so the
// DRAM stream runs at MLP=8 per warp (~168 outstanding lines/SM).
__global__ __launch_bounds__(256) void k_gemm1(
    const float4* __restrict__ x4,
    const float* __restrict__ W1,
    const float* __restrict__ b1,
    const float* __restrict__ Wg)
{
    __shared__ ulonglong2 ws[256][8];   // packed W1 pairs: ws[kp][jp]
    __shared__ float sWg[HID * HID];
    __shared__ float sb1[HID];

    int tid = threadIdx.x;
    for (int idx = tid; idx < 256 * 8; idx += 256) {
        int kp = idx >> 3, jp = idx & 7;
        int j0 = jp * 2;
        ulonglong2 v;
        v.x = pack2(W1[j0 * F_IN + 2 * kp],       W1[j0 * F_IN + 2 * kp + 1]);
        v.y = pack2(W1[(j0 + 1) * F_IN + 2 * kp], W1[(j0 + 1) * F_IN + 2 * kp + 1]);
        ws[kp][jp] = v;
    }
    for (int idx = tid; idx < HID * HID; idx += 256) sWg[idx] = Wg[idx];
    for (int idx = tid; idx < HID; idx += 256)       sb1[idx] = b1[idx];
    __syncthreads();

    int node = blockIdx.x * 256 + tid;
    bool valid = node < N_NODES;
    int nc = valid ? node : N_NODES - 1;

    unsigned long long acc[16];
    #pragma unroll
    for (int j = 0; j < 16; j++) acc[j] = 0ull;

    const float4* xr = x4 + (long long)nc * (F_IN / 4);

    #pragma unroll 1
    for (int q0 = 0; q0 < F_IN / 4; q0 += 8) {
        // prefetch batch: 8 independent LDG.128 issued back-to-back
        float4 xv[8];
        #pragma unroll
        for (int i = 0; i < 8; i++) xv[i] = __ldg(xr + q0 + i);
        // consume
        #pragma unroll
        for (int i = 0; i < 8; i++) {
            unsigned long long xa = pack2(xv[i].x, xv[i].y);
            unsigned long long xb = pack2(xv[i].z, xv[i].w);
            int kp = (q0 + i) * 2;
            #pragma unroll
            for (int jp = 0; jp < 8; jp++) {
                ulonglong2 w = ws[kp][jp];
                fma2(acc[2 * jp],     xa, w.x);
                fma2(acc[2 * jp + 1], xa, w.y);
            }
            #pragma unroll
            for (int jp = 0; jp < 8; jp++) {
                ulonglong2 w = ws[kp + 1][jp];
                fma2(acc[2 * jp],     xb, w.x);
                fma2(acc[2 * jp + 1], xb, w.y);
            }
        }
    }

    if (!valid) return;

    float h1[HID];
    #pragma unroll
    for (int j = 0; j < HID; j++) {
        float lo, hi;
        unpack2(acc[j], lo, hi);
        float v = lo + hi + sb1[j];
        h1[j] = v > 0.f ? v : 0.f;
    }

    float* hgp = g_hg + (long long)node * HID;
    #pragma unroll
    for (int j2 = 0; j2 < HID; j2 += 4) {
        float s0 = 0.f, s1 = 0.f, s2 = 0.f, s3 = 0.f;
        #pragma unroll
        for (int j = 0; j < HID; j++) {
            float hv = h1[j];
            s0 += hv * sWg[(j2 + 0) * HID + j];
            s1 += hv * sWg[(j2 + 1) * HID + j];
            s2 += hv * sWg[(j2 + 2) * HID + j];
            s3 += hv * sWg[(j2 + 3) * HID + j];
        }
        *(float4*)(hgp + j2) = make_float4(s0, s1, s2, s3);
    }
}

// ---------- fill bucketed CSR: 4 edges/thread, batched atomics then stores ----------
__global__ __launch_bounds__(256) void k_fill(const void* __restrict__ e) {
    int t = blockIdx.x * 256 + threadIdx.x;     // group of 4 edges
    if (t >= N_EDGES / 4) return;
    int s[4], d[4];
    if (g_is64) {
        const longlong4* ps = (const longlong4*)e;
        const longlong4* pd = (const longlong4*)((const long long*)e + N_EDGES);
        longlong4 a = ps[t];
        longlong4 b = pd[t];
        s[0] = (int)a.x; s[1] = (int)a.y; s[2] = (int)a.z; s[3] = (int)a.w;
        d[0] = (int)b.x; d[1] = (int)b.y; d[2] = (int)b.z; d[3] = (int)b.w;
    } else {
        const int4* ps = (const int4*)e;
        const int4* pd = (const int4*)((const int*)e + N_EDGES);
        int4 a = ps[t];
        int4 b = pd[t];
        s[0] = a.x; s[1] = a.y; s[2] = a.z; s[3] = a.w;
        d[0] = b.x; d[1] = b.y; d[2] = b.z; d[3] = b.w;
    }
    int pos[4];
    #pragma unroll
    for (int k = 0; k < 4; k++) pos[k] = atomicAdd(&g_cnt[d[k]], 1);
    #pragma unroll
    for (int k = 0; k < 4; k++)
        if (pos[k] < CAP) g_slots[d[k] * CAP + pos[k]] = s[k];
}

// ---------- hs = hg * rsqrt(deg)  (1 float4 per thread: 4x grid for latency) ----------
__global__ __launch_bounds__(256) void k_dinv() {
    int i = blockIdx.x * 256 + threadIdx.x;
    if (i >= N_NODES * 4) return;
    int node = i >> 2, q = i & 3;
    float dv = rsqrtf((float)(__ldg(&g_cnt[node]) + 1));   // +1 self loop
    float4 v = __ldg((const float4*)(g_hg + (long long)node * HID) + q);
    v.x *= dv; v.y *= dv; v.z *= dv; v.w *= dv;
    *((float4*)(g_hs + (long long)node * HID) + q) = v;
}

// ---------- fused gather + final ----------
__global__ __launch_bounds__(256) void k_gather_final(
    const float* __restrict__ W2,
    const float* __restrict__ b2,
    const float* __restrict__ bg,
    float* __restrict__ out)
{
    __shared__ float sW2[N_CLASSES * HID];
    __shared__ float sb2[N_CLASSES];
    __shared__ float sbg[HID];
    int tid = threadIdx.x;
    for (int i = tid; i < N_CLASSES * HID; i += 256) sW2[i] = W2[i];
    if (tid < N_CLASSES) sb2[tid] = b2[tid];
    if (tid < HID) sbg[tid] = bg[tid];
    __syncthreads();

    int warp = (blockIdx.x * 256 + tid) >> 5;
    if (warp >= N_NODES) return;
    int lane = tid & 31;
    int g = lane >> 2;        // edge group 0..7
    int f = lane & 3;         // float4 index 0..3

    int cnt = __ldg(&g_cnt[warp]);
    int m = cnt < CAP ? cnt : CAP;
    const int* slots = g_slots + warp * CAP;

    int s0 = 0, s1 = 0;
    if (lane < m)      s0 = __ldg(slots + lane);
    if (32 + lane < m) s1 = __ldg(slots + 32 + lane);

    float ax = 0.f, ay = 0.f, az = 0.f, aw = 0.f;
    int lim = m < 64 ? m : 64;
    #pragma unroll 4
    for (int e = 0; e < lim; e += 8) {
        int idx = e + g;
        int sv = (e < 32) ? __shfl_sync(0xFFFFFFFFu, s0, idx)
                          : __shfl_sync(0xFFFFFFFFu, s1, idx - 32);
        if (idx < lim) {
            float4 v = __ldg((const float4*)(g_hs + (long long)sv * HID) + f);
            ax += v.x; ay += v.y; az += v.z; aw += v.w;
        }
    }
    for (int e = 64; e < m; e += 8) {   // rare tail (deg > 64)
        int idx = e + g;
        if (idx < m) {
            int sv = __ldg(slots + idx);
            float4 v = __ldg((const float4*)(g_hs + (long long)sv * HID) + f);
            ax += v.x; ay += v.y; az += v.z; aw += v.w;
        }
    }
    #pragma unroll
    for (int off = 4; off < 32; off <<= 1) {
        ax += __shfl_xor_sync(0xFFFFFFFFu, ax, off);
        ay += __shfl_xor_sync(0xFFFFFFFFu, ay, off);
        az += __shfl_xor_sync(0xFFFFFFFFu, az, off);
        aw += __shfl_xor_sync(0xFFFFFFFFu, aw, off);
    }

    float4 self = __ldg((const float4*)(g_hs + (long long)warp * HID) + f);
    float dv = rsqrtf((float)(cnt + 1));
    float hp[4];
    {
        float t0 = (ax + self.x) * dv + sbg[4 * f + 0];
        float t1 = (ay + self.y) * dv + sbg[4 * f + 1];
        float t2 = (az + self.z) * dv + sbg[4 * f + 2];
        float t3 = (aw + self.w) * dv + sbg[4 * f + 3];
        hp[0] = t0 > 0.f ? t0 : 0.f;
        hp[1] = t1 > 0.f ? t1 : 0.f;
        hp[2] = t2 > 0.f ? t2 : 0.f;
        hp[3] = t3 > 0.f ? t3 : 0.f;
    }

    float h[HID];
    #pragma unroll
    for (int a = 0; a < 4; a++) {
        #pragma unroll
        for (int b = 0; b < 4; b++)
            h[a * 4 + b] = __shfl_sync(0xFFFFFFFFu, hp[b], a);
    }

    float l1 = sb2[lane];
    #pragma unroll
    for (int j = 0; j < HID; j++) l1 += h[j] * sW2[lane * HID + j];
    float l2 = -3.4e38f;
    if (lane < N_CLASSES - 32) {
        l2 = sb2[32 + lane];
        #pragma unroll
        for (int j = 0; j < HID; j++) l2 += h[j] * sW2[(32 + lane) * HID + j];
    }

    float mx = fmaxf(l1, l2);
    #pragma unroll
    for (int off = 16; off >= 1; off >>= 1)
        mx = fmaxf(mx, __shfl_xor_sync(0xFFFFFFFFu, mx, off));
    float ee = __expf(l1 - mx) + (lane < N_CLASSES - 32 ? __expf(l2 - mx) : 0.f);
    #pragma unroll
    for (int off = 16; off >= 1; off >>= 1)
        ee += __shfl_xor_sync(0xFFFFFFFFu, ee, off);
    float lse = __logf(ee) + mx;

    float* o = out + (long long)warp * N_CLASSES;
    o[lane] = l1 - lse;
    if (lane < N_CLASSES - 32) o[32 + lane] = l2 - lse;
}

extern "C" void kernel_launch(void* const* d_in, const int* in_sizes, int n_in,
                              void* d_out, int out_size) {
    const float* x  = (const float*)d_in[0];
    const void*  e  = d_in[1];
    const float* W1 = (const float*)d_in[2];
    const float* b1 = (const float*)d_in[3];
    const float* Wg = (const float*)d_in[4];
    const float* bg = (const float*)d_in[5];
    const float* W2 = (const float*)d_in[6];
    const float* b2 = (const float*)d_in[7];
    float* out = (float*)d_out;

    const int NB_N  = (N_NODES + 255) / 256;
    const int NB_D  = (N_NODES * 4 + 255) / 256;
    const int NB_E4 = (N_EDGES / 4 + 255) / 256;
    const int NB_G  = (N_NODES * 32 + 255) / 256;

    // Persistent fork resources: created on the first (eager) call, never
    // destroyed -> no stream/event create/destroy inside graph capture.
    static cudaStream_t s1 = 0;
    static cudaEvent_t ev0 = 0, ev1 = 0;
    static bool forked = false;
    static bool tried = false;
    if (!tried) {
        tried = true;
        forked =
            cudaStreamCreateWithFlags(&s1, cudaStreamNonBlocking) == cudaSuccess &&
            cudaEventCreateWithFlags(&ev0, cudaEventDisableTiming) == cudaSuccess &&
            cudaEventCreateWithFlags(&ev1, cudaEventDisableTiming) == cudaSuccess;
    }

    if (forked) {
        cudaEventRecord(ev0, 0);
        cudaStreamWaitEvent(s1, ev0, 0);
        // Branch A (side stream): dense GEMM (x-path, DRAM-bound)
        k_gemm1<<<NB_N, 256, 0, s1>>>((const float4*)x, W1, b1, Wg);
        // Branch B (main stream): CSR build (edge-path, LTS-atomic-bound)
        k_prep<<<NB_N, 256>>>(e);
        k_fill<<<NB_E4, 256>>>(e);
        // Join
        cudaEventRecord(ev1, s1);
        cudaStreamWaitEvent(0, ev1, 0);
    } else {
        k_prep<<<NB_N, 256>>>(e);
        k_gemm1<<<NB_N, 256>>>((const float4*)x, W1, b1, Wg);
        k_fill<<<NB_E4, 256>>>(e);
    }

    k_dinv<<<NB_D, 256>>>();
    k_gather_final<<<NB_G, 256>>>(W2, b2, bg, out);
}